// round 13
// baseline (speedup 1.0000x reference)
#include <cuda_runtime.h>
#include <cuda_fp16.h>

// PolyConvFrame: x_0 = x; x_L = tanh(alphas[L]) * (Adj_norm @ x_{L-1}), L=1..3
// Adj_norm val_e = dinv[row_e]*w_e*dinv[col_e], dinv = deg>0 ? rsqrt(deg) : 0.
// Output [N, DEPTH+1, 64] fp32, out[i*256 + L*64 + d].
//
// R13: unordered CSR allocation (block base via one atomicAdd; per-row
// start/end stored explicitly) collapses the 3-phase scan into one kernel
// that also computes dinv and the dinv-prescaled fp16 mirror of x. CSR keeps
// raw {col, w}; spmm gathers prescaled mirrors and applies aL*dinv[row] at
// the end. SpMM uses pair-gathers: half-warps process edge pairs, one LDG.64
// per 2 edges (half the gather instructions). Launch #4 = spmm<1> (profiled).

#define N_NODE 100000
#define N_EDGE 1600000
#define D_FEAT 64
#define DEPTH  3
#define OUT_STRIDE 256                               // (DEPTH+1)*D_FEAT
#define SCAN_B ((N_NODE + 255) / 256)                // 391 blocks

__device__ float g_deg[N_NODE];                      // zeroed by k_scan after use
__device__ int   g_cnt[N_NODE];                      // zeroed by spmm<1> epilogue
__device__ int   g_rowstart[N_NODE];
__device__ int   g_rowend[N_NODE];                   // start + padded count
__device__ int   g_cursor[N_NODE];
__device__ float g_dinv[N_NODE];
__device__ unsigned int g_grand;                     // zeroed by spmm<1> epilogue
// +N_NODE for even-padding, +8 guard (reads past a row end are w-predicated)
__device__ __align__(16) int2 g_csr[N_EDGE + N_NODE + 8];
__device__ __align__(128) __half g_mX[(size_t)N_NODE * D_FEAT];  // dinv*x
__device__ __align__(128) __half g_mA[(size_t)N_NODE * D_FEAT];  // dinv*x1
__device__ __align__(128) __half g_mB[(size_t)N_NODE * D_FEAT];  // dinv*x2

// --- per-block dtype probe (JAX x64-off coerces int64->int32) ---------------
__device__ __forceinline__ int probe_is64_block(const void* eidx) {
    __shared__ int s_is64;
    if (threadIdx.x < 32) {
        const long long* p = (const long long*)eidx;
        long long v = p[(size_t)threadIdx.x * (N_EDGE / 32)];
        unsigned bad = __ballot_sync(0xFFFFFFFFu, v < 0 || v >= N_NODE);
        if (threadIdx.x == 0) s_is64 = (bad == 0);
    }
    __syncthreads();
    return s_is64;
}

__device__ __forceinline__ int clampi(int v) {
    v = v < 0 ? 0 : v;
    return v >= N_NODE ? N_NODE - 1 : v;
}
__device__ __forceinline__ int ld_row(const void* e, int i, int is64) {
    long long v = is64 ? ((const long long*)e)[i] : (long long)((const int*)e)[i];
    return clampi((int)v);
}
__device__ __forceinline__ int ld_col(const void* e, int i, int is64) {
    long long v = is64 ? ((const long long*)e)[N_EDGE + i]
                       : (long long)((const int*)e)[N_EDGE + i];
    return clampi((int)v);
}

// Launch 1: deg[row] += w ; cnt[row] += 1.
__global__ void k_count(const void* __restrict__ eidx,
                        const float* __restrict__ w) {
    int is64 = probe_is64_block(eidx);
    int e = blockIdx.x * blockDim.x + threadIdx.x;
    if (e >= N_EDGE) return;
    int r = ld_row(eidx, e, is64);
    atomicAdd(&g_deg[r], w[e]);
    atomicAdd(&g_cnt[r], 1);
}

// Launch 2: unordered CSR allocation + dinv + fp16 mirror of x.
// Block scans its 256 padded counts, grabs a global base with one atomicAdd
// (segment ORDER is irrelevant; only start/end matter), writes rowstart/
// rowend/cursor, pad slots, dinv (zeroing g_deg), and m_X = dinv*x.
__global__ void k_scan(const float* __restrict__ x) {
    __shared__ int sh[256];
    __shared__ float sh_dinv[256];
    __shared__ unsigned sh_base;
    int tid = threadIdx.x;
    int i = blockIdx.x * 256 + tid;

    int cnt = (i < N_NODE) ? g_cnt[i] : 0;
    int c = (cnt + 1) & ~1;                          // even-padded count
    sh[tid] = c;
    __syncthreads();
    #pragma unroll
    for (int off = 1; off < 256; off <<= 1) {        // inclusive Hillis-Steele
        int t = (tid >= off) ? sh[tid - off] : 0;
        __syncthreads();
        sh[tid] += t;
        __syncthreads();
    }
    int incl = sh[tid];
    int total = sh[255];
    if (tid == 0) sh_base = atomicAdd(&g_grand, (unsigned)total);
    __syncthreads();

    float dv = 0.f;
    if (i < N_NODE) {
        int s = (int)sh_base + incl - c;
        g_rowstart[i] = s;
        g_cursor[i]   = s;
        g_rowend[i]   = s + c;
        if (cnt & 1) g_csr[s + cnt] = make_int2(0, 0);   // zero-weight pad
        float deg = g_deg[i];
        dv = deg > 0.f ? rsqrtf(deg) : 0.f;
        g_dinv[i] = dv;
        g_deg[i] = 0.f;                              // restore zero-invariant
    }
    sh_dinv[tid] = dv;
    __syncthreads();

    // m_X = fp16(dinv * x) for this block's 256 nodes (coalesced).
    int base_node = blockIdx.x * 256;
    #pragma unroll 1
    for (int t = tid; t < 256 * 32; t += 256) {
        int nl = t >> 5, el = t & 31;
        int node = base_node + nl;
        if (node < N_NODE) {
            float2 v = ((const float2*)x)[(size_t)node * 32 + el];
            float d = sh_dinv[nl];
            ((__half2*)g_mX)[(size_t)node * 32 + el] =
                __floats2half2_rn(d * v.x, d * v.y);
        }
    }
}

// Launch 3: bucket raw {col, w} into CSR (no deg reads, no rsqrt).
__global__ void k_fill(const void* __restrict__ eidx,
                       const float* __restrict__ w) {
    int is64 = probe_is64_block(eidx);
    int e = blockIdx.x * blockDim.x + threadIdx.x;
    if (e >= N_EDGE) return;
    int r = ld_row(eidx, e, is64);
    int c = ld_col(eidx, e, is64);
    int pos = atomicAdd(&g_cursor[r], 1);
    g_csr[pos] = make_int2(c, __float_as_int(w[e]));
}

// One batch of 8 CSR entries at 16B-aligned even index i. Half-warps process
// edge pairs: lane (half, fl) loads 4 halfs (LDG.64) of edge i+2k+half.
template <int PRED>
__device__ __forceinline__ void pair_batch8(const __half* __restrict__ src,
                                            int i, int e, int half, int fl,
                                            float4& acc) {
    const int4* p = (const int4*)(g_csr + i);
    int4 q[4];
    #pragma unroll
    for (int k = 0; k < 4; k++) q[k] = __ldg(p + k);

    int   col[4];
    float wv[4];
    #pragma unroll
    for (int k = 0; k < 4; k++) {
        col[k] = half ? q[k].z : q[k].x;
        wv[k]  = __int_as_float(half ? q[k].w : q[k].y);
        if (PRED) {
            if (i + 2 * k + half >= e) { wv[k] = 0.f; col[k] = 0; }
        }
    }
    uint2 raw[4];
    #pragma unroll
    for (int k = 0; k < 4; k++)
        raw[k] = __ldg((const uint2*)(src + (size_t)col[k] * D_FEAT) + fl);
    #pragma unroll
    for (int k = 0; k < 4; k++) {
        float2 f0 = __half22float2(*(const __half2*)&raw[k].x);
        float2 f1 = __half22float2(*(const __half2*)&raw[k].y);
        acc.x = fmaf(wv[k], f0.x, acc.x);
        acc.y = fmaf(wv[k], f0.y, acc.y);
        acc.z = fmaf(wv[k], f1.x, acc.z);
        acc.w = fmaf(wv[k], f1.y, acc.w);
    }
}

// Launches 4-6: SpMM layer L. Warp per row; pair-gathers; fp32 accumulate;
// x_L[r] = aL*dinv[r]*acc; mirror_L[r] = dinv[r]*x_L[r].
template <int L>
__global__ void __launch_bounds__(256)
k_spmm(const float* __restrict__ x, float* __restrict__ out,
       const float* __restrict__ alphas) {
    int warp = (blockIdx.x * blockDim.x + threadIdx.x) >> 5;
    if (warp >= N_NODE) return;
    int lane = threadIdx.x & 31;
    int half = lane >> 4;
    int fl   = lane & 15;

    int s = __ldg(&g_rowstart[warp]);                // even, 16B-aligned
    int e = __ldg(&g_rowend[warp]);                  // even

    const __half* __restrict__ src =
        (L == 1) ? g_mX : (L == 2) ? g_mA : g_mB;

    float4 acc = make_float4(0.f, 0.f, 0.f, 0.f);
    int i = s;
    int nfull = s + ((e - s) & ~7);
    #pragma unroll 1
    for (; i < nfull; i += 8)
        pair_batch8<0>(src, i, e, half, fl, acc);
    if (i < e)                                       // 2..6 entries (even)
        pair_batch8<1>(src, i, e, half, fl, acc);

    // fold odd-edge half into even-edge half
    acc.x += __shfl_down_sync(0xFFFFFFFFu, acc.x, 16);
    acc.y += __shfl_down_sync(0xFFFFFFFFu, acc.y, 16);
    acc.z += __shfl_down_sync(0xFFFFFFFFu, acc.z, 16);
    acc.w += __shfl_down_sync(0xFFFFFFFFu, acc.w, 16);

    float dinv = __ldg(&g_dinv[warp]);
    float aL = tanhf(__ldg(&alphas[L]));
    float sc = aL * dinv;

    if (half == 0) {
        float4 r4 = make_float4(sc * acc.x, sc * acc.y, sc * acc.z, sc * acc.w);
        ((float4*)(out + (size_t)warp * OUT_STRIDE + (size_t)L * D_FEAT))[fl] = r4;
        if (L < 3) {
            __half* mdst = (L == 1) ? g_mA : g_mB;
            __half2 h0 = __floats2half2_rn(dinv * r4.x, dinv * r4.y);
            __half2 h1 = __floats2half2_rn(dinv * r4.z, dinv * r4.w);
            uint2 pk;
            pk.x = *(const unsigned*)&h0;
            pk.y = *(const unsigned*)&h1;
            ((uint2*)(mdst + (size_t)warp * D_FEAT))[fl] = pk;
        }
    }

    if (L == 1) {
        // restore zero-invariants + x -> out slice 0 (fp32)
        if (lane == 0) g_cnt[warp] = 0;
        if (warp == 0 && lane == 0) g_grand = 0u;
        ((float2*)(out + (size_t)warp * OUT_STRIDE))[lane] =
            __ldg((const float2*)(x + (size_t)warp * D_FEAT) + lane);
    }
}

extern "C" void kernel_launch(void* const* d_in, const int* in_sizes, int n_in,
                              void* d_out, int out_size) {
    const float* x      = (const float*)d_in[0];
    const void*  eidx   = d_in[1];                   // [2, E], int32 or int64
    const float* w      = (const float*)d_in[2];
    const float* alphas = (const float*)d_in[3];
    float* out = (float*)d_out;

    const int TB = 256;
    const int EB = (N_EDGE + TB - 1) / TB;
    const int SPMM_B = (N_NODE * 32 + TB - 1) / TB;  // warp per row

    k_count<<<EB, TB>>>(eidx, w);                    // launch 1
    k_scan<<<SCAN_B, 256>>>(x);                      // launch 2
    k_fill<<<EB, TB>>>(eidx, w);                     // launch 3
    k_spmm<1><<<SPMM_B, TB>>>(x, out, alphas);       // launch 4 (profiled)
    k_spmm<2><<<SPMM_B, TB>>>(x, out, alphas);       // launch 5
    k_spmm<3><<<SPMM_B, TB>>>(x, out, alphas);       // launch 6
}

// round 14
// speedup vs baseline: 1.1559x; 1.1559x over previous
#include <cuda_runtime.h>
#include <cuda_fp16.h>

// PolyConvFrame: x_0 = x; x_L = tanh(alphas[L]) * (Adj_norm @ x_{L-1}), L=1..3
// Adj_norm val_e = dinv[row_e]*w_e*dinv[col_e], dinv = deg>0 ? rsqrt(deg) : 0.
// Output [N, DEPTH+1, 64] fp32, out[i*256 + L*64 + d].
//
// R14 = R13 preprocessing + R12 SpMM core.
//  - unordered CSR alloc: one fused kernel (block scan + one atomicAdd base)
//    also computes dinv and the dinv-prescaled fp16 mirror of x.
//  - fill stores raw {col, w} (no deg reads / rsqrt in the hot pass).
//  - SpMM: warp per row, batch-8 half2 gathers (one row per warp-instruction
//    = wavefront-optimal for 128B rows), int4 CSR loads on even-aligned rows,
//    tail-only predication; epilogue applies aL*dinv[row], writes fp32 slice
//    and dinv-prescaled fp16 mirror for the next layer.

#define N_NODE 100000
#define N_EDGE 1600000
#define D_FEAT 64
#define DEPTH  3
#define OUT_STRIDE 256                               // (DEPTH+1)*D_FEAT
#define SCAN_B ((N_NODE + 255) / 256)                // 391 blocks

__device__ float g_deg[N_NODE];                      // zeroed by k_scan after use
__device__ int   g_cnt[N_NODE];                      // zeroed by spmm<1> epilogue
__device__ int   g_rowstart[N_NODE];
__device__ int   g_rowend[N_NODE];                   // start + padded count
__device__ int   g_cursor[N_NODE];
__device__ float g_dinv[N_NODE];
__device__ unsigned int g_grand;                     // zeroed by spmm<1> epilogue
// +N_NODE for even-padding, +8 guard (read-only, stays zero / predicated)
__device__ __align__(16) int2 g_csr[N_EDGE + N_NODE + 8];
__device__ __align__(128) __half g_mX[(size_t)N_NODE * D_FEAT];  // dinv*x
__device__ __align__(128) __half g_mA[(size_t)N_NODE * D_FEAT];  // dinv*x1
__device__ __align__(128) __half g_mB[(size_t)N_NODE * D_FEAT];  // dinv*x2

// --- per-block dtype probe (JAX x64-off coerces int64->int32) ---------------
__device__ __forceinline__ int probe_is64_block(const void* eidx) {
    __shared__ int s_is64;
    if (threadIdx.x < 32) {
        const long long* p = (const long long*)eidx;
        long long v = p[(size_t)threadIdx.x * (N_EDGE / 32)];
        unsigned bad = __ballot_sync(0xFFFFFFFFu, v < 0 || v >= N_NODE);
        if (threadIdx.x == 0) s_is64 = (bad == 0);
    }
    __syncthreads();
    return s_is64;
}

__device__ __forceinline__ int clampi(int v) {
    v = v < 0 ? 0 : v;
    return v >= N_NODE ? N_NODE - 1 : v;
}
__device__ __forceinline__ int ld_row(const void* e, int i, int is64) {
    long long v = is64 ? ((const long long*)e)[i] : (long long)((const int*)e)[i];
    return clampi((int)v);
}
__device__ __forceinline__ int ld_col(const void* e, int i, int is64) {
    long long v = is64 ? ((const long long*)e)[N_EDGE + i]
                       : (long long)((const int*)e)[N_EDGE + i];
    return clampi((int)v);
}

// Launch 1: deg[row] += w ; cnt[row] += 1.
__global__ void k_count(const void* __restrict__ eidx,
                        const float* __restrict__ w) {
    int is64 = probe_is64_block(eidx);
    int e = blockIdx.x * blockDim.x + threadIdx.x;
    if (e >= N_EDGE) return;
    int r = ld_row(eidx, e, is64);
    atomicAdd(&g_deg[r], w[e]);
    atomicAdd(&g_cnt[r], 1);
}

// Launch 2: unordered CSR allocation + dinv + fp16 mirror of x.
__global__ void k_scan(const float* __restrict__ x) {
    __shared__ int sh[256];
    __shared__ float sh_dinv[256];
    __shared__ unsigned sh_base;
    int tid = threadIdx.x;
    int i = blockIdx.x * 256 + tid;

    int cnt = (i < N_NODE) ? g_cnt[i] : 0;
    int c = (cnt + 1) & ~1;                          // even-padded count
    sh[tid] = c;
    __syncthreads();
    #pragma unroll
    for (int off = 1; off < 256; off <<= 1) {        // inclusive Hillis-Steele
        int t = (tid >= off) ? sh[tid - off] : 0;
        __syncthreads();
        sh[tid] += t;
        __syncthreads();
    }
    int incl = sh[tid];
    int total = sh[255];
    if (tid == 0) sh_base = atomicAdd(&g_grand, (unsigned)total);
    __syncthreads();

    float dv = 0.f;
    if (i < N_NODE) {
        int s = (int)sh_base + incl - c;
        g_rowstart[i] = s;
        g_cursor[i]   = s;
        g_rowend[i]   = s + c;
        if (cnt & 1) g_csr[s + cnt] = make_int2(0, 0);   // zero-weight pad
        float deg = g_deg[i];
        dv = deg > 0.f ? rsqrtf(deg) : 0.f;
        g_dinv[i] = dv;
        g_deg[i] = 0.f;                              // restore zero-invariant
    }
    sh_dinv[tid] = dv;
    __syncthreads();

    // m_X = fp16(dinv * x) for this block's 256 nodes (coalesced).
    int base_node = blockIdx.x * 256;
    #pragma unroll 1
    for (int t = tid; t < 256 * 32; t += 256) {
        int nl = t >> 5, el = t & 31;
        int node = base_node + nl;
        if (node < N_NODE) {
            float2 v = ((const float2*)x)[(size_t)node * 32 + el];
            float d = sh_dinv[nl];
            ((__half2*)g_mX)[(size_t)node * 32 + el] =
                __floats2half2_rn(d * v.x, d * v.y);
        }
    }
}

// Launch 3: bucket raw {col, w} into CSR (no deg reads, no rsqrt).
__global__ void k_fill(const void* __restrict__ eidx,
                       const float* __restrict__ w) {
    int is64 = probe_is64_block(eidx);
    int e = blockIdx.x * blockDim.x + threadIdx.x;
    if (e >= N_EDGE) return;
    int r = ld_row(eidx, e, is64);
    int c = ld_col(eidx, e, is64);
    int pos = atomicAdd(&g_cursor[r], 1);
    g_csr[pos] = make_int2(c, __float_as_int(w[e]));
}

// One batch of 8 CSR entries at 16B-aligned even index i; half2 gathers
// (one 128B row per warp-instruction — wavefront-optimal).
template <int PRED>
__device__ __forceinline__ void spmm_batch8(const __half* __restrict__ src,
                                            int i, int e, int lane,
                                            float& ax, float& ay) {
    const int4* p = (const int4*)(g_csr + i);
    int4 q[4];
    #pragma unroll
    for (int k = 0; k < 4; k++) q[k] = __ldg(p + k);

    int   col[8];
    float w8[8];
    #pragma unroll
    for (int k = 0; k < 4; k++) {
        col[2 * k + 0] = q[k].x; w8[2 * k + 0] = __int_as_float(q[k].y);
        col[2 * k + 1] = q[k].z; w8[2 * k + 1] = __int_as_float(q[k].w);
    }
    if (PRED) {
        #pragma unroll
        for (int k = 0; k < 8; k++) {
            if (i + k >= e) { w8[k] = 0.f; col[k] = 0; }
        }
    }
    float2 f[8];
    #pragma unroll
    for (int k = 0; k < 8; k++)
        f[k] = __half22float2(
            __ldg((const __half2*)(src + (size_t)col[k] * D_FEAT) + lane));
    #pragma unroll
    for (int k = 0; k < 8; k++) {
        ax = fmaf(w8[k], f[k].x, ax);
        ay = fmaf(w8[k], f[k].y, ay);
    }
}

// Launches 4-6: SpMM layer L on prescaled mirrors; epilogue scales by
// aL*dinv[row]; writes fp32 slice L and (L<3) the next prescaled mirror.
template <int L>
__global__ void __launch_bounds__(256)
k_spmm(const float* __restrict__ x, float* __restrict__ out,
       const float* __restrict__ alphas) {
    int warp = (blockIdx.x * blockDim.x + threadIdx.x) >> 5;
    if (warp >= N_NODE) return;
    int lane = threadIdx.x & 31;

    int s = __ldg(&g_rowstart[warp]);                // even, 16B-aligned
    int e = __ldg(&g_rowend[warp]);                  // even (incl. pad)

    const __half* __restrict__ src =
        (L == 1) ? g_mX : (L == 2) ? g_mA : g_mB;

    float ax = 0.f, ay = 0.f;
    int i = s;
    int nfull = s + ((e - s) & ~7);
    #pragma unroll 1
    for (; i < nfull; i += 8)
        spmm_batch8<0>(src, i, e, lane, ax, ay);
    if (i < e)                                       // 2..6 entries (even)
        spmm_batch8<1>(src, i, e, lane, ax, ay);

    float dinv = __ldg(&g_dinv[warp]);
    float aL = tanhf(__ldg(&alphas[L]));
    float sc = aL * dinv;
    float rx = sc * ax, ry = sc * ay;

    ((float2*)(out + (size_t)warp * OUT_STRIDE + (size_t)L * D_FEAT))[lane] =
        make_float2(rx, ry);

    if (L == 1)
        ((__half2*)(g_mA + (size_t)warp * D_FEAT))[lane] =
            __floats2half2_rn(dinv * rx, dinv * ry);
    if (L == 2)
        ((__half2*)(g_mB + (size_t)warp * D_FEAT))[lane] =
            __floats2half2_rn(dinv * rx, dinv * ry);

    if (L == 1) {
        if (lane == 0) g_cnt[warp] = 0;              // restore zero-invariant
        if (warp == 0 && lane == 0) g_grand = 0u;
        ((float2*)(out + (size_t)warp * OUT_STRIDE))[lane] =
            __ldg((const float2*)(x + (size_t)warp * D_FEAT) + lane);
    }
}

extern "C" void kernel_launch(void* const* d_in, const int* in_sizes, int n_in,
                              void* d_out, int out_size) {
    const float* x      = (const float*)d_in[0];
    const void*  eidx   = d_in[1];                   // [2, E], int32 or int64
    const float* w      = (const float*)d_in[2];
    const float* alphas = (const float*)d_in[3];
    float* out = (float*)d_out;

    const int TB = 256;
    const int EB = (N_EDGE + TB - 1) / TB;
    const int SPMM_B = (N_NODE * 32 + TB - 1) / TB;  // warp per row

    k_count<<<EB, TB>>>(eidx, w);                    // launch 1
    k_scan<<<SCAN_B, 256>>>(x);                      // launch 2
    k_fill<<<EB, TB>>>(eidx, w);                     // launch 3
    k_spmm<1><<<SPMM_B, TB>>>(x, out, alphas);       // launch 4 (profiled)
    k_spmm<2><<<SPMM_B, TB>>>(x, out, alphas);       // launch 5
    k_spmm<3><<<SPMM_B, TB>>>(x, out, alphas);       // launch 6
}

// round 15
// speedup vs baseline: 1.2286x; 1.0629x over previous
#include <cuda_runtime.h>
#include <cuda_fp16.h>

// PolyConvFrame: x_0 = x; x_L = tanh(alphas[L]) * (Adj_norm @ x_{L-1}), L=1..3
// Adj_norm val_e = dinv[row_e]*w_e*dinv[col_e], dinv = deg>0 ? rsqrt(deg) : 0.
// Output [N, DEPTH+1, 64] fp32, out[i*256 + L*64 + d].
//
// R15 = R14 with:
//  - k_count: ONE packed 64-bit atomic per edge (count in bits[48:64),
//    fixed-point sum(w)*2^32 in bits[0:48)) instead of float+int atomics.
//  - x -> out slice 0 moved into k_scan (which already reads all of x for the
//    mirror); spmm<1> no longer re-reads x.
// SpMM core unchanged (warp/row, int4 CSR, batch-8 half2 gathers: proven).

#define N_NODE 100000
#define N_EDGE 1600000
#define D_FEAT 64
#define DEPTH  3
#define OUT_STRIDE 256                               // (DEPTH+1)*D_FEAT
#define SCAN_B ((N_NODE + 255) / 256)                // 391 blocks

__device__ unsigned long long g_pack[N_NODE];        // zeroed by k_scan after use
__device__ int   g_rowstart[N_NODE];
__device__ int   g_rowend[N_NODE];                   // start + padded count
__device__ int   g_cursor[N_NODE];
__device__ float g_dinv[N_NODE];
__device__ unsigned int g_grand;                     // zeroed by spmm<1> epilogue
// +N_NODE for even-padding, +8 guard (read-only, stays zero / predicated)
__device__ __align__(16) int2 g_csr[N_EDGE + N_NODE + 8];
__device__ __align__(128) __half g_mX[(size_t)N_NODE * D_FEAT];  // dinv*x
__device__ __align__(128) __half g_mA[(size_t)N_NODE * D_FEAT];  // dinv*x1
__device__ __align__(128) __half g_mB[(size_t)N_NODE * D_FEAT];  // dinv*x2

// --- per-block dtype probe (JAX x64-off coerces int64->int32) ---------------
__device__ __forceinline__ int probe_is64_block(const void* eidx) {
    __shared__ int s_is64;
    if (threadIdx.x < 32) {
        const long long* p = (const long long*)eidx;
        long long v = p[(size_t)threadIdx.x * (N_EDGE / 32)];
        unsigned bad = __ballot_sync(0xFFFFFFFFu, v < 0 || v >= N_NODE);
        if (threadIdx.x == 0) s_is64 = (bad == 0);
    }
    __syncthreads();
    return s_is64;
}

__device__ __forceinline__ int clampi(int v) {
    v = v < 0 ? 0 : v;
    return v >= N_NODE ? N_NODE - 1 : v;
}
__device__ __forceinline__ int ld_row(const void* e, int i, int is64) {
    long long v = is64 ? ((const long long*)e)[i] : (long long)((const int*)e)[i];
    return clampi((int)v);
}
__device__ __forceinline__ int ld_col(const void* e, int i, int is64) {
    long long v = is64 ? ((const long long*)e)[N_EDGE + i]
                       : (long long)((const int*)e)[N_EDGE + i];
    return clampi((int)v);
}

// Launch 1: one packed atomic per edge: pack[row] += (1<<48) | (w * 2^32).
__global__ void k_count(const void* __restrict__ eidx,
                        const float* __restrict__ w) {
    int is64 = probe_is64_block(eidx);
    int e = blockIdx.x * blockDim.x + threadIdx.x;
    if (e >= N_EDGE) return;
    int r = ld_row(eidx, e, is64);
    unsigned long long add =
        (1ull << 48) | (unsigned long long)(w[e] * 4294967296.0f);
    atomicAdd(&g_pack[r], add);
}

// Launch 2: unordered CSR allocation + dinv + fp16 mirror of x + out slice 0.
__global__ void k_scan(const float* __restrict__ x, float* __restrict__ out) {
    __shared__ int sh[256];
    __shared__ float sh_dinv[256];
    __shared__ unsigned sh_base;
    int tid = threadIdx.x;
    int i = blockIdx.x * 256 + tid;

    int cnt = 0;
    float deg = 0.f;
    if (i < N_NODE) {
        unsigned long long p = g_pack[i];
        cnt = (int)(p >> 48);
        deg = (float)((double)(p & 0xFFFFFFFFFFFFull) * (1.0 / 4294967296.0));
        g_pack[i] = 0ull;                            // restore zero-invariant
    }
    int c = (cnt + 1) & ~1;                          // even-padded count
    sh[tid] = c;
    __syncthreads();
    #pragma unroll
    for (int off = 1; off < 256; off <<= 1) {        // inclusive Hillis-Steele
        int t = (tid >= off) ? sh[tid - off] : 0;
        __syncthreads();
        sh[tid] += t;
        __syncthreads();
    }
    int incl = sh[tid];
    int total = sh[255];
    if (tid == 0) sh_base = atomicAdd(&g_grand, (unsigned)total);
    __syncthreads();

    float dv = 0.f;
    if (i < N_NODE) {
        int s = (int)sh_base + incl - c;
        g_rowstart[i] = s;
        g_cursor[i]   = s;
        g_rowend[i]   = s + c;
        if (cnt & 1) g_csr[s + cnt] = make_int2(0, 0);   // zero-weight pad
        dv = deg > 0.f ? rsqrtf(deg) : 0.f;
        g_dinv[i] = dv;
    }
    sh_dinv[tid] = dv;
    __syncthreads();

    // m_X = fp16(dinv * x) and out slice 0 = x, for this block's 256 nodes.
    int base_node = blockIdx.x * 256;
    #pragma unroll 1
    for (int t = tid; t < 256 * 32; t += 256) {
        int nl = t >> 5, el = t & 31;
        int node = base_node + nl;
        if (node < N_NODE) {
            float2 v = ((const float2*)x)[(size_t)node * 32 + el];
            float d = sh_dinv[nl];
            ((__half2*)g_mX)[(size_t)node * 32 + el] =
                __floats2half2_rn(d * v.x, d * v.y);
            ((float2*)(out + (size_t)node * OUT_STRIDE))[el] = v;
        }
    }
}

// Launch 3: bucket raw {col, w} into CSR (no deg reads, no rsqrt).
__global__ void k_fill(const void* __restrict__ eidx,
                       const float* __restrict__ w) {
    int is64 = probe_is64_block(eidx);
    int e = blockIdx.x * blockDim.x + threadIdx.x;
    if (e >= N_EDGE) return;
    int r = ld_row(eidx, e, is64);
    int c = ld_col(eidx, e, is64);
    int pos = atomicAdd(&g_cursor[r], 1);
    g_csr[pos] = make_int2(c, __float_as_int(w[e]));
}

// One batch of 8 CSR entries at 16B-aligned even index i; half2 gathers
// (one 128B row per warp-instruction — wavefront-optimal).
template <int PRED>
__device__ __forceinline__ void spmm_batch8(const __half* __restrict__ src,
                                            int i, int e, int lane,
                                            float& ax, float& ay) {
    const int4* p = (const int4*)(g_csr + i);
    int4 q[4];
    #pragma unroll
    for (int k = 0; k < 4; k++) q[k] = __ldg(p + k);

    int   col[8];
    float w8[8];
    #pragma unroll
    for (int k = 0; k < 4; k++) {
        col[2 * k + 0] = q[k].x; w8[2 * k + 0] = __int_as_float(q[k].y);
        col[2 * k + 1] = q[k].z; w8[2 * k + 1] = __int_as_float(q[k].w);
    }
    if (PRED) {
        #pragma unroll
        for (int k = 0; k < 8; k++) {
            if (i + k >= e) { w8[k] = 0.f; col[k] = 0; }
        }
    }
    float2 f[8];
    #pragma unroll
    for (int k = 0; k < 8; k++)
        f[k] = __half22float2(
            __ldg((const __half2*)(src + (size_t)col[k] * D_FEAT) + lane));
    #pragma unroll
    for (int k = 0; k < 8; k++) {
        ax = fmaf(w8[k], f[k].x, ax);
        ay = fmaf(w8[k], f[k].y, ay);
    }
}

// Launches 4-6: SpMM layer L on prescaled mirrors; epilogue scales by
// aL*dinv[row]; writes fp32 slice L and (L<3) the next prescaled mirror.
template <int L>
__global__ void __launch_bounds__(256)
k_spmm(float* __restrict__ out, const float* __restrict__ alphas) {
    int warp = (blockIdx.x * blockDim.x + threadIdx.x) >> 5;
    if (warp >= N_NODE) return;
    int lane = threadIdx.x & 31;

    int s = __ldg(&g_rowstart[warp]);                // even, 16B-aligned
    int e = __ldg(&g_rowend[warp]);                  // even (incl. pad)

    const __half* __restrict__ src =
        (L == 1) ? g_mX : (L == 2) ? g_mA : g_mB;

    float ax = 0.f, ay = 0.f;
    int i = s;
    int nfull = s + ((e - s) & ~7);
    #pragma unroll 1
    for (; i < nfull; i += 8)
        spmm_batch8<0>(src, i, e, lane, ax, ay);
    if (i < e)                                       // 2..6 entries (even)
        spmm_batch8<1>(src, i, e, lane, ax, ay);

    float dinv = __ldg(&g_dinv[warp]);
    float aL = tanhf(__ldg(&alphas[L]));
    float sc = aL * dinv;
    float rx = sc * ax, ry = sc * ay;

    ((float2*)(out + (size_t)warp * OUT_STRIDE + (size_t)L * D_FEAT))[lane] =
        make_float2(rx, ry);

    if (L == 1)
        ((__half2*)(g_mA + (size_t)warp * D_FEAT))[lane] =
            __floats2half2_rn(dinv * rx, dinv * ry);
    if (L == 2)
        ((__half2*)(g_mB + (size_t)warp * D_FEAT))[lane] =
            __floats2half2_rn(dinv * rx, dinv * ry);

    if (L == 1 && warp == 0 && lane == 0) g_grand = 0u;   // zero-invariant
}

extern "C" void kernel_launch(void* const* d_in, const int* in_sizes, int n_in,
                              void* d_out, int out_size) {
    const float* x      = (const float*)d_in[0];
    const void*  eidx   = d_in[1];                   // [2, E], int32 or int64
    const float* w      = (const float*)d_in[2];
    const float* alphas = (const float*)d_in[3];
    float* out = (float*)d_out;

    const int TB = 256;
    const int EB = (N_EDGE + TB - 1) / TB;
    const int SPMM_B = (N_NODE * 32 + TB - 1) / TB;  // warp per row

    k_count<<<EB, TB>>>(eidx, w);                    // launch 1
    k_scan<<<SCAN_B, 256>>>(x, out);                 // launch 2
    k_fill<<<EB, TB>>>(eidx, w);                     // launch 3
    k_spmm<1><<<SPMM_B, TB>>>(out, alphas);          // launch 4 (profiled)
    k_spmm<2><<<SPMM_B, TB>>>(out, alphas);          // launch 5
    k_spmm<3><<<SPMM_B, TB>>>(out, alphas);          // launch 6
}